// round 13
// baseline (speedup 1.0000x reference)
#include <cuda_runtime.h>

static constexpr int H    = 96;
static constexpr int PW2  = 292;          // k_node packed width: 3*96 src + 4 attn scalars
static constexpr int NCG2 = PW2 / 4;      // 73 float4 groups
static constexpr int NSG  = H / 4;        // 24 float4 groups per type row
static constexpr int NMAXC = 100000;
static constexpr int TNF  = 16;           // k_final node tile

// ------------------------ device scratch (no allocs allowed) ------------------------
__device__ float4   g_W2[H * NCG2];                    // packed node weight [k][col/4]
__device__ float    g_C[3 * H];                        // per-type constant c_t
__device__ __align__(128) float4 g_src4[(size_t)3 * NMAXC * NSG];  // src-half, 384B rows
__device__ float4   g_attn[NMAXC];                     // (a_s0, a_d0, a_s1, a_d1)
__device__ float4   g_acc4[(size_t)3 * NMAXC * NSG];   // scatter accumulators
__device__ float    g_den[3 * NMAXC];                  // softmax denominators / mean counts
__device__ float4   g_Wf[384 * NSG];                   // folded final weight [k][j/4]
__device__ float4   g_Mneg[3 * H * NSG];               // -(Wdst_t @ Wu_t), [t][k][j/4]

// ------------------------ f32x2 helpers ------------------------
__device__ __forceinline__ void fma2(unsigned long long& c, unsigned long long a, unsigned long long b) {
    asm("fma.rn.f32x2 %0, %1, %2, %0;" : "+l"(c) : "l"(a), "l"(b));
}
__device__ __forceinline__ unsigned long long pk2(float x, float y) {
    unsigned long long r;
    asm("mov.b64 %0, {%1, %2};" : "=l"(r) : "f"(x), "f"(y));
    return r;
}
__device__ __forceinline__ void upk2(float& x, float& y, unsigned long long v) {
    asm("mov.b64 {%0, %1}, %2;" : "=f"(x), "=f"(y) : "l"(v));
}
__device__ __forceinline__ void ldg2x64(unsigned long long& a, unsigned long long& b, const void* p) {
    asm("ld.global.v2.u64 {%0, %1}, [%2];" : "=l"(a), "=l"(b) : "l"(p));
}
__device__ __forceinline__ void stg2x64(void* p, unsigned long long a, unsigned long long b) {
    asm("st.global.v2.u64 [%0], {%1, %2};" :: "l"(p), "l"(a), "l"(b) : "memory");
}

// ------------------------ K_prep: pack weights, fold dst-half, zero accumulators ------------------------
__global__ void k_prep(const float* __restrict__ Wm0, const float* __restrict__ Wm1,
                       const float* __restrict__ Wm2,
                       const float* __restrict__ bm0, const float* __restrict__ bm1,
                       const float* __restrict__ bm2,
                       const float* __restrict__ ef0, const float* __restrict__ ef1,
                       const float* __restrict__ ef2,
                       const float* __restrict__ Wn0, const float* __restrict__ Wa0,
                       const float* __restrict__ Wn1, const float* __restrict__ Wa1,
                       const float* __restrict__ Wu, int N) {
    const float* Wm[3] = {Wm0, Wm1, Wm2};
    const float* bm[3] = {bm0, bm1, bm2};
    const float* ef[3] = {ef0, ef1, ef2};
    int tid = blockIdx.x * blockDim.x + threadIdx.x;
    int stride = blockDim.x * gridDim.x;

    // ---- zero accumulators ----
    {
        int accq = 3 * N * NSG;
        float4 z4 = make_float4(0.f, 0.f, 0.f, 0.f);
        for (int i = tid; i < accq; i += stride) g_acc4[i] = z4;
        for (int i = tid; i < 3 * N; i += stride) g_den[i] = 0.f;
    }

    // ---- W2: src halves + attention fold, [96 x 292] ----
    float* W2 = (float*)g_W2;
    for (int idx = tid; idx < H * PW2; idx += stride) {
        int k = idx / PW2, c = idx % PW2;
        float v;
        if (c < 288) {                     // src-half rows [0:96) of Wm_t
            int t = c / 96, j = c % 96;
            v = Wm[t][k * 96 + j];
        } else {                           // folded attention vectors Wn @ Wa-half
            int which = c - 288;           // 0:a_s0 1:a_d0 2:a_s1 3:a_d1
            const float* Wn = (which < 2) ? Wn0 : Wn1;
            const float* Wa = (which < 2) ? Wa0 : Wa1;
            int off = (which & 1) * 32;
            float s = 0.f;
            #pragma unroll
            for (int j = 0; j < 32; j++) s += Wn[k * 32 + j] * Wa[off + j];
            v = s;
        }
        W2[idx] = v;
    }
    // ---- c_t[j] = bm_t[j] + ef_t . Wm_t[192:208, j] ----
    for (int idx = tid; idx < 3 * H; idx += stride) {
        int t = idx / 96, j = idx % 96;
        float s = bm[t][j];
        #pragma unroll
        for (int i = 0; i < 16; i++) s += ef[t][i] * Wm[t][(192 + i) * 96 + j];
        g_C[idx] = s;
    }
    // ---- Wf[k][j]: k<96 -> Wu_h + sum_t Wdst_t@Wu_t ; k>=96 -> Wu row ----
    float* Wf = (float*)g_Wf;
    for (int idx = tid; idx < 384 * H; idx += stride) {
        int k = idx / 96, j = idx % 96;
        float v = Wu[k * 96 + j];
        if (k < 96) {
            #pragma unroll
            for (int t = 0; t < 3; t++) {
                const float* wm = Wm[t];
                float s = 0.f;
                #pragma unroll 8
                for (int i = 0; i < 96; i++)
                    s += wm[(96 + k) * 96 + i] * Wu[(96 + 96 * t + i) * 96 + j];
                v += s;
            }
        }
        Wf[k * 96 + j] = v;
    }
    // ---- Mneg[t][k][j] = -(Wdst_t @ Wu_t)[k][j]  (empty-node correction) ----
    float* Mn = (float*)g_Mneg;
    for (int idx = tid; idx < 3 * H * H; idx += stride) {
        int t = idx / (96 * 96), r = idx % (96 * 96);
        int k = r / 96, j = r % 96;
        const float* wm = Wm[t];
        float s = 0.f;
        #pragma unroll 8
        for (int i = 0; i < 96; i++)
            s += wm[(96 + k) * 96 + i] * Wu[(96 + 96 * t + i) * 96 + j];
        Mn[(t * 96 + k) * 96 + j] = -s;
    }
}

// ------------------------ K_node: packed GEMM [N x 96] @ [96 x 292] ------------------------
// Register-tiled: 8 nodes per thread per W column-group, f32x2 packed FMA.
static constexpr int TN = 64;              // node tile
__global__ void __launch_bounds__(256) k_node(const float* __restrict__ h, int N) {
    __shared__ unsigned long long hs2[TN * H];   // 48KB
    int n0 = blockIdx.x * TN;
    int tid = threadIdx.x;

    for (int idx = tid; idx < TN * (H / 4); idx += 256) {   // 1536 float4
        int n = idx / (H / 4);
        int c4 = idx % (H / 4);
        float4 v = make_float4(0.f, 0.f, 0.f, 0.f);
        if (n0 + n < N) v = ((const float4*)h)[(size_t)(n0 + n) * (H / 4) + c4];
        int base = n * H + c4 * 4;
        hs2[base + 0] = pk2(v.x, v.x);
        hs2[base + 1] = pk2(v.y, v.y);
        hs2[base + 2] = pk2(v.z, v.z);
        hs2[base + 3] = pk2(v.w, v.w);
    }
    __syncthreads();

    for (int task = tid; task < NCG2 * (TN / 8); task += 256) {
        int cg = task % NCG2;              // adjacent threads -> adjacent cg (coalesced W)
        int nb = (task / NCG2) * 8;        // node sub-tile base
        const float4* Wp = g_W2 + cg;
        const unsigned long long* hp = &hs2[nb * H];

        unsigned long long a0[8], a1[8];
        #pragma unroll
        for (int i = 0; i < 8; i++) { a0[i] = 0ull; a1[i] = 0ull; }

        #pragma unroll 4
        for (int k = 0; k < H; k++) {
            unsigned long long w0, w1;
            ldg2x64(w0, w1, Wp + (size_t)k * NCG2);
            #pragma unroll
            for (int i = 0; i < 8; i++) {
                unsigned long long hh = hp[i * H + k];   // LDS.64 broadcast
                fma2(a0[i], hh, w0);
                fma2(a1[i], hh, w1);
            }
        }

        if (cg < 72) {
            int t = cg / NSG, off = cg % NSG;
            #pragma unroll
            for (int i = 0; i < 8; i++) {
                int n = n0 + nb + i;
                if (n < N)
                    stg2x64(&g_src4[((size_t)t * N + n) * NSG + off], a0[i], a1[i]);
            }
        } else {                            // cg==72: attention scalars (cols 288-291)
            #pragma unroll
            for (int i = 0; i < 8; i++) {
                int n = n0 + nb + i;
                if (n < N) stg2x64(&g_attn[n], a0[i], a1[i]);
            }
        }
    }
}

// ------------------------ K_scatter: 4 edges per warp, batched-MLP gather/red ------------------------
__global__ void __launch_bounds__(256) k_scatter(
        const int* __restrict__ src0, const int* __restrict__ dst0,
        const int* __restrict__ src1, const int* __restrict__ dst1,
        const int* __restrict__ src2, const int* __restrict__ dst2,
        int E, int N) {
    const unsigned FULL = 0xffffffffu;
    int gw   = (blockIdx.x * blockDim.x + threadIdx.x) >> 5;
    int lane = threadIdx.x & 31;
    int wpt  = (E + 3) >> 2;               // warps per edge type
    if (gw >= 3 * wpt) return;
    int t  = gw / wpt;
    int e0 = (gw - t * wpt) * 4;

    const int* sp = (t == 0) ? src0 : (t == 1) ? src1 : src2;
    const int* dp = (t == 0) ? dst0 : (t == 1) ? dst1 : dst2;
    const float4* sb = g_src4 + (size_t)t * N * NSG;   // 384B-aligned rows
    float4* ab = g_acc4 + (size_t)t * N * NSG;

    // lanes 0-3 load src[e0+lane], lanes 4-7 load dst[e0+lane-4]  (MLP=8)
    int idx = 0;
    if (lane < 8) {
        int e = e0 + (lane & 3);
        if (e < E) idx = (lane < 4) ? sp[e] : dp[e];
    }
    int dsh = __shfl_down_sync(FULL, idx, 4);   // lanes 0-3: their edge's dst

    // lanes 0-3: per-edge weight + den atomic
    float w = 1.f;
    if (lane < 4 && e0 + lane < E) {
        if (t < 2) {
            float4 as = g_attn[idx];
            float4 ad = g_attn[dsh];
            float x  = t ? (as.z + ad.w) : (as.x + ad.y);
            float sc = (x > 0.f) ? x : 0.01f * x;    // leaky_relu(0.01)
            w = __expf(sc);
        }
        atomicAdd(&g_den[t * N + dsh], w);
    }

    // batched gathers: 4 independent LDG.128 chains in flight
    float4 v[4];
    int    dj[4];
    float  wj[4];
    #pragma unroll
    for (int j = 0; j < 4; j++) {
        int s  = __shfl_sync(FULL, idx, j);
        dj[j]  = __shfl_sync(FULL, idx, 4 + j);
        wj[j]  = __shfl_sync(FULL, w, j);
        if (lane < 24 && e0 + j < E)
            v[j] = sb[(size_t)s * NSG + lane];
    }
    #pragma unroll
    for (int j = 0; j < 4; j++) {
        if (lane < 24 && e0 + j < E) {
            float4* a = &ab[(size_t)dj[j] * NSG + lane];
            float ww = wj[j];
            asm volatile("red.global.add.v4.f32 [%0], {%1,%2,%3,%4};"
                         :: "l"(a), "f"(v[j].x * ww), "f"(v[j].y * ww),
                            "f"(v[j].z * ww), "f"(v[j].w * ww)
                         : "memory");
        }
    }
}

// ------------------------ K_final v3: k_node-shaped [N x 384] @ [384 x 96] ------------------------
// 16-node tile, 96 threads; x dup-packed (x,x) in 48KB smem; compact Wf from global (L1-hot).
// Zero packing movs in the inner loop; 8 independent u64 acc chains per thread.
__global__ void __launch_bounds__(96) k_final(const float* __restrict__ h,
                                              const float* __restrict__ bu,
                                              float* __restrict__ out, int N) {
    __shared__ unsigned long long xs2[TNF * 384];   // (x,x) pairs, 48KB
    __shared__ float rden[TNF * 3];
    int n0 = blockIdx.x * TNF;
    int tid = threadIdx.x;
    const float* g_acc = (const float*)g_acc4;

    // stage reciprocals once per (node, type); 0 marks an empty mailbox
    if (tid < TNF * 3) {
        int n = tid / 3, t = tid % 3;
        float den = (n0 + n < N) ? g_den[t * N + n0 + n] : 1.f;
        rden[n * 3 + t] = (den > 0.f) ? 1.0f / den : 0.f;
    }
    __syncthreads();

    // assemble x, store duplicated (x,x)
    for (int ep = tid; ep < TNF * 384; ep += 96) {
        int n = ep / 384, c = ep % 384;
        int gn = n0 + n;
        float v = 0.f;
        if (gn < N) {
            if (c < 96) {
                v = h[(size_t)gn * 96 + c];
            } else {
                int t = (c - 96) / 96, j = (c - 96) % 96;
                float rd = rden[n * 3 + t];
                if (rd > 0.f) {
                    float accv = g_acc[((size_t)t * N + gn) * H + j];
                    v = fmaf(accv, rd, g_C[t * 96 + j]);
                }
            }
        }
        xs2[ep] = pk2(v, v);
    }
    __syncthreads();

    {
        int cg = tid % 24;                 // output float4 group (coalesced W)
        int nb = (tid / 24) * 4;           // 4 nodes per thread
        const float4* Wp = g_Wf + cg;
        float4 b = ((const float4*)bu)[cg];

        unsigned long long a0[4], a1[4];
        #pragma unroll
        for (int i = 0; i < 4; i++) { a0[i] = pk2(b.x, b.y); a1[i] = pk2(b.z, b.w); }

        #pragma unroll 4
        for (int k = 0; k < 384; k++) {
            unsigned long long w0, w1;
            ldg2x64(w0, w1, Wp + (size_t)k * 24);
            #pragma unroll
            for (int i = 0; i < 4; i++) {
                unsigned long long hh = xs2[(nb + i) * 384 + k];   // LDS.64 broadcast
                fma2(a0[i], hh, w0);
                fma2(a1[i], hh, w1);
            }
        }

        #pragma unroll
        for (int i = 0; i < 4; i++) {
            int n = n0 + nb + i;
            if (n < N) {
                // rare empty-mailbox correction: add x @ Mneg_t (removes folded dst part)
                #pragma unroll
                for (int t = 0; t < 3; t++) {
                    if (rden[(nb + i) * 3 + t] == 0.f) {
                        const float4* Mp = g_Mneg + (size_t)t * H * 24 + cg;
                        for (int k = 0; k < H; k++) {
                            unsigned long long m0, m1;
                            ldg2x64(m0, m1, Mp + (size_t)k * 24);
                            unsigned long long hh = xs2[(nb + i) * 384 + k];  // (x,x)
                            fma2(a0[i], hh, m0);
                            fma2(a1[i], hh, m1);
                        }
                    }
                }
                float4 r;
                upk2(r.x, r.y, a0[i]);
                upk2(r.z, r.w, a1[i]);
                r.x = fmaxf(r.x, 0.f); r.y = fmaxf(r.y, 0.f);
                r.z = fmaxf(r.z, 0.f); r.w = fmaxf(r.w, 0.f);
                ((float4*)out)[(size_t)n * 24 + cg] = r;
            }
        }
    }
}

// ------------------------ launch ------------------------
extern "C" void kernel_launch(void* const* d_in, const int* in_sizes, int n_in,
                              void* d_out, int out_size) {
    const float* h    = (const float*)d_in[0];
    const int*   src0 = (const int*)d_in[1];
    const int*   dst0 = (const int*)d_in[2];
    const int*   src1 = (const int*)d_in[3];
    const int*   dst1 = (const int*)d_in[4];
    const int*   src2 = (const int*)d_in[5];
    const int*   dst2 = (const int*)d_in[6];
    const float* Wm0  = (const float*)d_in[7];
    const float* bm0  = (const float*)d_in[8];
    const float* ef0  = (const float*)d_in[9];
    const float* Wm1  = (const float*)d_in[10];
    const float* bm1  = (const float*)d_in[11];
    const float* ef1  = (const float*)d_in[12];
    const float* Wm2  = (const float*)d_in[13];
    const float* bm2  = (const float*)d_in[14];
    const float* ef2  = (const float*)d_in[15];
    const float* Wn0  = (const float*)d_in[16];
    const float* Wa0  = (const float*)d_in[17];
    const float* Wn1  = (const float*)d_in[18];
    const float* Wa1  = (const float*)d_in[19];
    const float* Wu   = (const float*)d_in[20];
    const float* bu   = (const float*)d_in[21];

    int N = in_sizes[0] / H;
    int E = in_sizes[1];

    k_prep<<<256, 256>>>(Wm0, Wm1, Wm2, bm0, bm1, bm2, ef0, ef1, ef2,
                         Wn0, Wa0, Wn1, Wa1, Wu, N);
    k_node<<<(N + TN - 1) / TN, 256>>>(h, N);
    int wpt = (E + 3) / 4;
    long warps = 3L * wpt;
    k_scatter<<<(unsigned)((warps + 7) / 8), 256>>>(src0, dst0, src1, dst1, src2, dst2, E, N);
    k_final<<<(N + TNF - 1) / TNF, 96>>>(h, bu, (float*)d_out, N);
}

// round 14
// speedup vs baseline: 1.2205x; 1.2205x over previous
#include <cuda_runtime.h>

static constexpr int H    = 96;
static constexpr int PW2  = 292;          // k_node packed width: 3*96 src + 4 attn scalars
static constexpr int NCG2 = PW2 / 4;      // 73 float4 groups
static constexpr int NSG  = H / 4;        // 24 float4 groups per type row
static constexpr int NMAXC = 100000;
static constexpr int TF   = 64;           // k_final node tile
static constexpr int SMF  = 96 * TF * 8 + TF * 3 * 4;  // 49920 B dynamic smem

// ------------------------ device scratch (no allocs allowed) ------------------------
__device__ float4   g_W2[H * NCG2];                    // packed node weight [k][col/4]
__device__ float    g_C[3 * H];                        // per-type constant c_t
__device__ __align__(128) float4 g_src4[(size_t)3 * NMAXC * NSG];  // src-half, 384B rows
__device__ float4   g_attn[NMAXC];                     // (a_s0, a_d0, a_s1, a_d1)
__device__ float4   g_acc4[(size_t)3 * NMAXC * NSG];   // scatter accumulators
__device__ float    g_den[3 * NMAXC];                  // softmax denominators / mean counts
__device__ float4   g_Wf[384 * NSG];                   // folded final weight [k][j/4]
__device__ float4   g_Mneg[3 * H * NSG];               // -(Wdst_t @ Wu_t), [t][k][j/4]

// ------------------------ f32x2 helpers ------------------------
__device__ __forceinline__ void fma2(unsigned long long& c, unsigned long long a, unsigned long long b) {
    asm("fma.rn.f32x2 %0, %1, %2, %0;" : "+l"(c) : "l"(a), "l"(b));
}
__device__ __forceinline__ unsigned long long pk2(float x, float y) {
    unsigned long long r;
    asm("mov.b64 %0, {%1, %2};" : "=l"(r) : "f"(x), "f"(y));
    return r;
}
__device__ __forceinline__ void upk2(float& x, float& y, unsigned long long v) {
    asm("mov.b64 {%0, %1}, %2;" : "=f"(x), "=f"(y) : "l"(v));
}
__device__ __forceinline__ void ldg2x64(unsigned long long& a, unsigned long long& b, const void* p) {
    asm("ld.global.v2.u64 {%0, %1}, [%2];" : "=l"(a), "=l"(b) : "l"(p));
}
__device__ __forceinline__ void stg2x64(void* p, unsigned long long a, unsigned long long b) {
    asm("st.global.v2.u64 [%0], {%1, %2};" :: "l"(p), "l"(a), "l"(b) : "memory");
}

// ------------------------ K_prep: pack weights, fold dst-half, zero accumulators ------------------------
__global__ void k_prep(const float* __restrict__ Wm0, const float* __restrict__ Wm1,
                       const float* __restrict__ Wm2,
                       const float* __restrict__ bm0, const float* __restrict__ bm1,
                       const float* __restrict__ bm2,
                       const float* __restrict__ ef0, const float* __restrict__ ef1,
                       const float* __restrict__ ef2,
                       const float* __restrict__ Wn0, const float* __restrict__ Wa0,
                       const float* __restrict__ Wn1, const float* __restrict__ Wa1,
                       const float* __restrict__ Wu, int N) {
    const float* Wm[3] = {Wm0, Wm1, Wm2};
    const float* bm[3] = {bm0, bm1, bm2};
    const float* ef[3] = {ef0, ef1, ef2};
    int tid = blockIdx.x * blockDim.x + threadIdx.x;
    int stride = blockDim.x * gridDim.x;

    // ---- zero accumulators ----
    {
        int accq = 3 * N * NSG;
        float4 z4 = make_float4(0.f, 0.f, 0.f, 0.f);
        for (int i = tid; i < accq; i += stride) g_acc4[i] = z4;
        for (int i = tid; i < 3 * N; i += stride) g_den[i] = 0.f;
    }

    // ---- W2: src halves + attention fold, [96 x 292] ----
    float* W2 = (float*)g_W2;
    for (int idx = tid; idx < H * PW2; idx += stride) {
        int k = idx / PW2, c = idx % PW2;
        float v;
        if (c < 288) {                     // src-half rows [0:96) of Wm_t
            int t = c / 96, j = c % 96;
            v = Wm[t][k * 96 + j];
        } else {                           // folded attention vectors Wn @ Wa-half
            int which = c - 288;           // 0:a_s0 1:a_d0 2:a_s1 3:a_d1
            const float* Wn = (which < 2) ? Wn0 : Wn1;
            const float* Wa = (which < 2) ? Wa0 : Wa1;
            int off = (which & 1) * 32;
            float s = 0.f;
            #pragma unroll
            for (int j = 0; j < 32; j++) s += Wn[k * 32 + j] * Wa[off + j];
            v = s;
        }
        W2[idx] = v;
    }
    // ---- c_t[j] = bm_t[j] + ef_t . Wm_t[192:208, j] ----
    for (int idx = tid; idx < 3 * H; idx += stride) {
        int t = idx / 96, j = idx % 96;
        float s = bm[t][j];
        #pragma unroll
        for (int i = 0; i < 16; i++) s += ef[t][i] * Wm[t][(192 + i) * 96 + j];
        g_C[idx] = s;
    }
    // ---- Wf[k][j]: k<96 -> Wu_h + sum_t Wdst_t@Wu_t ; k>=96 -> Wu row ----
    float* Wf = (float*)g_Wf;
    for (int idx = tid; idx < 384 * H; idx += stride) {
        int k = idx / 96, j = idx % 96;
        float v = Wu[k * 96 + j];
        if (k < 96) {
            #pragma unroll
            for (int t = 0; t < 3; t++) {
                const float* wm = Wm[t];
                float s = 0.f;
                #pragma unroll 8
                for (int i = 0; i < 96; i++)
                    s += wm[(96 + k) * 96 + i] * Wu[(96 + 96 * t + i) * 96 + j];
                v += s;
            }
        }
        Wf[k * 96 + j] = v;
    }
    // ---- Mneg[t][k][j] = -(Wdst_t @ Wu_t)[k][j]  (empty-node correction) ----
    float* Mn = (float*)g_Mneg;
    for (int idx = tid; idx < 3 * H * H; idx += stride) {
        int t = idx / (96 * 96), r = idx % (96 * 96);
        int k = r / 96, j = r % 96;
        const float* wm = Wm[t];
        float s = 0.f;
        #pragma unroll 8
        for (int i = 0; i < 96; i++)
            s += wm[(96 + k) * 96 + i] * Wu[(96 + 96 * t + i) * 96 + j];
        Mn[(t * 96 + k) * 96 + j] = -s;
    }
}

// ------------------------ K_node: packed GEMM [N x 96] @ [96 x 292] ------------------------
// Register-tiled: 8 nodes per thread per W column-group, f32x2 packed FMA.
static constexpr int TN = 64;              // node tile
__global__ void __launch_bounds__(256) k_node(const float* __restrict__ h, int N) {
    __shared__ unsigned long long hs2[TN * H];   // 48KB
    int n0 = blockIdx.x * TN;
    int tid = threadIdx.x;

    for (int idx = tid; idx < TN * (H / 4); idx += 256) {   // 1536 float4
        int n = idx / (H / 4);
        int c4 = idx % (H / 4);
        float4 v = make_float4(0.f, 0.f, 0.f, 0.f);
        if (n0 + n < N) v = ((const float4*)h)[(size_t)(n0 + n) * (H / 4) + c4];
        int base = n * H + c4 * 4;
        hs2[base + 0] = pk2(v.x, v.x);
        hs2[base + 1] = pk2(v.y, v.y);
        hs2[base + 2] = pk2(v.z, v.z);
        hs2[base + 3] = pk2(v.w, v.w);
    }
    __syncthreads();

    for (int task = tid; task < NCG2 * (TN / 8); task += 256) {
        int cg = task % NCG2;              // adjacent threads -> adjacent cg (coalesced W)
        int nb = (task / NCG2) * 8;        // node sub-tile base
        const float4* Wp = g_W2 + cg;
        const unsigned long long* hp = &hs2[nb * H];

        unsigned long long a0[8], a1[8];
        #pragma unroll
        for (int i = 0; i < 8; i++) { a0[i] = 0ull; a1[i] = 0ull; }

        #pragma unroll 4
        for (int k = 0; k < H; k++) {
            unsigned long long w0, w1;
            ldg2x64(w0, w1, Wp + (size_t)k * NCG2);
            #pragma unroll
            for (int i = 0; i < 8; i++) {
                unsigned long long hh = hp[i * H + k];   // LDS.64 broadcast
                fma2(a0[i], hh, w0);
                fma2(a1[i], hh, w1);
            }
        }

        if (cg < 72) {
            int t = cg / NSG, off = cg % NSG;
            #pragma unroll
            for (int i = 0; i < 8; i++) {
                int n = n0 + nb + i;
                if (n < N)
                    stg2x64(&g_src4[((size_t)t * N + n) * NSG + off], a0[i], a1[i]);
            }
        } else {                            // cg==72: attention scalars (cols 288-291)
            #pragma unroll
            for (int i = 0; i < 8; i++) {
                int n = n0 + nb + i;
                if (n < N) stg2x64(&g_attn[n], a0[i], a1[i]);
            }
        }
    }
}

// ------------------------ K_scatter: 4 edges per warp, batched-MLP gather/red ------------------------
__global__ void __launch_bounds__(256) k_scatter(
        const int* __restrict__ src0, const int* __restrict__ dst0,
        const int* __restrict__ src1, const int* __restrict__ dst1,
        const int* __restrict__ src2, const int* __restrict__ dst2,
        int E, int N) {
    const unsigned FULL = 0xffffffffu;
    int gw   = (blockIdx.x * blockDim.x + threadIdx.x) >> 5;
    int lane = threadIdx.x & 31;
    int wpt  = (E + 3) >> 2;               // warps per edge type
    if (gw >= 3 * wpt) return;
    int t  = gw / wpt;
    int e0 = (gw - t * wpt) * 4;

    const int* sp = (t == 0) ? src0 : (t == 1) ? src1 : src2;
    const int* dp = (t == 0) ? dst0 : (t == 1) ? dst1 : dst2;
    const float4* sb = g_src4 + (size_t)t * N * NSG;   // 384B-aligned rows
    float4* ab = g_acc4 + (size_t)t * N * NSG;

    // lanes 0-3 load src[e0+lane], lanes 4-7 load dst[e0+lane-4]  (MLP=8)
    int idx = 0;
    if (lane < 8) {
        int e = e0 + (lane & 3);
        if (e < E) idx = (lane < 4) ? sp[e] : dp[e];
    }
    int dsh = __shfl_down_sync(FULL, idx, 4);   // lanes 0-3: their edge's dst

    // lanes 0-3: per-edge weight + den atomic
    float w = 1.f;
    if (lane < 4 && e0 + lane < E) {
        if (t < 2) {
            float4 as = g_attn[idx];
            float4 ad = g_attn[dsh];
            float x  = t ? (as.z + ad.w) : (as.x + ad.y);
            float sc = (x > 0.f) ? x : 0.01f * x;    // leaky_relu(0.01)
            w = __expf(sc);
        }
        atomicAdd(&g_den[t * N + dsh], w);
    }

    // batched gathers: 4 independent LDG.128 chains in flight
    float4 v[4];
    int    dj[4];
    float  wj[4];
    #pragma unroll
    for (int j = 0; j < 4; j++) {
        int s  = __shfl_sync(FULL, idx, j);
        dj[j]  = __shfl_sync(FULL, idx, 4 + j);
        wj[j]  = __shfl_sync(FULL, w, j);
        if (lane < 24 && e0 + j < E)
            v[j] = sb[(size_t)s * NSG + lane];
    }
    #pragma unroll
    for (int j = 0; j < 4; j++) {
        if (lane < 24 && e0 + j < E) {
            float4* a = &ab[(size_t)dj[j] * NSG + lane];
            float ww = wj[j];
            asm volatile("red.global.add.v4.f32 [%0], {%1,%2,%3,%4};"
                         :: "l"(a), "f"(v[j].x * ww), "f"(v[j].y * ww),
                            "f"(v[j].z * ww), "f"(v[j].w * ww)
                         : "memory");
        }
    }
}

// ------------------------ K_final v4: k_node-shaped, K-chunked [N x 384] @ [384 x 96] ------------------------
// 64-node tile, 192 threads, 4 K-chunks of 96. Per chunk: stage dup-packed (x,x) chunk (48KB),
// then k_node inner loop (1 LDG + 8 LDS.64 + 16 FFMA2 per k). Accumulators persist across chunks.
__global__ void __launch_bounds__(192) k_final(const float* __restrict__ h,
                                               const float* __restrict__ bu,
                                               float* __restrict__ out, int N) {
    extern __shared__ unsigned long long dynsm[];
    unsigned long long* xs2 = dynsm;                    // [96][TF] dup pairs, 48KB
    float* rden = (float*)(dynsm + 96 * TF);            // [TF][3]
    int n0 = blockIdx.x * TF;
    int tid = threadIdx.x;

    // stage reciprocals once per (node, type); 0 marks an empty mailbox. TF*3 == 192.
    {
        int n = tid / 3, t = tid % 3;
        float den = (n0 + n < N) ? g_den[t * N + n0 + n] : 1.f;
        rden[n * 3 + t] = (den > 0.f) ? 1.0f / den : 0.f;
    }

    int cg = tid % 24;                     // output float4 group (coalesced W)
    int nb = (tid / 24) * 8;               // 8 nodes per thread

    float4 b = ((const float4*)bu)[cg];
    unsigned long long a0[8], a1[8];
    #pragma unroll
    for (int i = 0; i < 8; i++) { a0[i] = pk2(b.x, b.y); a1[i] = pk2(b.z, b.w); }

    for (int c = 0; c < 4; c++) {
        __syncthreads();                   // first iter: publishes rden; later: retire xs2 readers
        // stage chunk c: 64 nodes x 24 float4 cols
        for (int ep = tid; ep < TF * 24; ep += 192) {
            int n = ep / 24, j4 = ep % 24;
            int gn = n0 + n;
            float4 v = make_float4(0.f, 0.f, 0.f, 0.f);
            if (gn < N) {
                if (c == 0) {
                    v = ((const float4*)h)[(size_t)gn * 24 + j4];
                } else {
                    int t = c - 1;
                    float rd = rden[n * 3 + t];
                    if (rd > 0.f) {
                        float4 a = g_acc4[((size_t)t * N + gn) * NSG + j4];
                        float4 C = ((const float4*)g_C)[t * 24 + j4];
                        v.x = fmaf(a.x, rd, C.x); v.y = fmaf(a.y, rd, C.y);
                        v.z = fmaf(a.z, rd, C.z); v.w = fmaf(a.w, rd, C.w);
                    }
                }
            }
            int jb = j4 * 4;
            xs2[(jb + 0) * TF + n] = pk2(v.x, v.x);
            xs2[(jb + 1) * TF + n] = pk2(v.y, v.y);
            xs2[(jb + 2) * TF + n] = pk2(v.z, v.z);
            xs2[(jb + 3) * TF + n] = pk2(v.w, v.w);
        }
        __syncthreads();

        const float4* Wp = g_Wf + (size_t)c * 96 * 24 + cg;
        #pragma unroll 4
        for (int k = 0; k < 96; k++) {
            unsigned long long w0, w1;
            ldg2x64(w0, w1, Wp + (size_t)k * 24);
            const unsigned long long* xk = &xs2[k * TF + nb];
            #pragma unroll
            for (int i = 0; i < 8; i++) {
                fma2(a0[i], xk[i], w0);    // LDS.64 broadcast
                fma2(a1[i], xk[i], w1);
            }
        }
    }

    // epilogue: rare empty-mailbox correction (x_h @ Mneg_t), relu, store
    #pragma unroll
    for (int i = 0; i < 8; i++) {
        int n = n0 + nb + i;
        if (n < N) {
            #pragma unroll
            for (int t = 0; t < 3; t++) {
                if (rden[(nb + i) * 3 + t] == 0.f) {
                    const float4* Mp = g_Mneg + (size_t)t * H * 24 + cg;
                    for (int k = 0; k < H; k++) {
                        unsigned long long m0, m1;
                        ldg2x64(m0, m1, Mp + (size_t)k * 24);
                        float hv = h[(size_t)n * 96 + k];
                        unsigned long long hh = pk2(hv, hv);
                        fma2(a0[i], hh, m0);
                        fma2(a1[i], hh, m1);
                    }
                }
            }
            float4 r;
            upk2(r.x, r.y, a0[i]);
            upk2(r.z, r.w, a1[i]);
            r.x = fmaxf(r.x, 0.f); r.y = fmaxf(r.y, 0.f);
            r.z = fmaxf(r.z, 0.f); r.w = fmaxf(r.w, 0.f);
            ((float4*)out)[(size_t)n * 24 + cg] = r;
        }
    }
}

// ------------------------ launch ------------------------
extern "C" void kernel_launch(void* const* d_in, const int* in_sizes, int n_in,
                              void* d_out, int out_size) {
    const float* h    = (const float*)d_in[0];
    const int*   src0 = (const int*)d_in[1];
    const int*   dst0 = (const int*)d_in[2];
    const int*   src1 = (const int*)d_in[3];
    const int*   dst1 = (const int*)d_in[4];
    const int*   src2 = (const int*)d_in[5];
    const int*   dst2 = (const int*)d_in[6];
    const float* Wm0  = (const float*)d_in[7];
    const float* bm0  = (const float*)d_in[8];
    const float* ef0  = (const float*)d_in[9];
    const float* Wm1  = (const float*)d_in[10];
    const float* bm1  = (const float*)d_in[11];
    const float* ef1  = (const float*)d_in[12];
    const float* Wm2  = (const float*)d_in[13];
    const float* bm2  = (const float*)d_in[14];
    const float* ef2  = (const float*)d_in[15];
    const float* Wn0  = (const float*)d_in[16];
    const float* Wa0  = (const float*)d_in[17];
    const float* Wn1  = (const float*)d_in[18];
    const float* Wa1  = (const float*)d_in[19];
    const float* Wu   = (const float*)d_in[20];
    const float* bu   = (const float*)d_in[21];

    int N = in_sizes[0] / H;
    int E = in_sizes[1];

    static bool attr_set = false;
    if (!attr_set) {
        cudaFuncSetAttribute(k_final, cudaFuncAttributeMaxDynamicSharedMemorySize, SMF);
        attr_set = true;
    }

    k_prep<<<256, 256>>>(Wm0, Wm1, Wm2, bm0, bm1, bm2, ef0, ef1, ef2,
                         Wn0, Wa0, Wn1, Wa1, Wu, N);
    k_node<<<(N + TN - 1) / TN, 256>>>(h, N);
    int wpt = (E + 3) / 4;
    long warps = 3L * wpt;
    k_scatter<<<(unsigned)((warps + 7) / 8), 256>>>(src0, dst0, src1, dst1, src2, dst2, E, N);
    k_final<<<(N + TF - 1) / TF, 192, SMF>>>(h, bu, (float*)d_out, N);
}

// round 15
// speedup vs baseline: 1.5385x; 1.2605x over previous
#include <cuda_runtime.h>

static constexpr int H    = 96;
static constexpr int PW2  = 292;          // k_node packed width: 3*96 src + 4 attn scalars
static constexpr int NCG2 = PW2 / 4;      // 73 float4 groups
static constexpr int NSG  = H / 4;        // 24 float4 groups per type row
static constexpr int NMAXC = 100000;
static constexpr int TF   = 48;           // k_final node tile
static constexpr int SMF  = 96 * TF * 8 + TF * 3 * 4;  // 37440 B dynamic smem

// ------------------------ device scratch (no allocs allowed) ------------------------
__device__ float4   g_W2[(H + 1) * NCG2];              // packed node weight [k][col/4] (+1 pad row for prefetch)
__device__ float    g_C[3 * H];                        // per-type constant c_t
__device__ __align__(128) float4 g_src4[(size_t)3 * NMAXC * NSG];  // src-half, 384B rows
__device__ float4   g_attn[NMAXC];                     // (a_s0, a_d0, a_s1, a_d1)
__device__ float4   g_acc4[(size_t)3 * NMAXC * NSG];   // scatter accumulators
__device__ float    g_den[3 * NMAXC];                  // softmax denominators / mean counts
__device__ float4   g_Wf[(384 + 1) * NSG];             // folded final weight (+1 pad row for prefetch)
__device__ float4   g_Mneg[3 * H * NSG];               // -(Wdst_t @ Wu_t), [t][k][j/4]

// ------------------------ f32x2 helpers ------------------------
__device__ __forceinline__ void fma2(unsigned long long& c, unsigned long long a, unsigned long long b) {
    asm("fma.rn.f32x2 %0, %1, %2, %0;" : "+l"(c) : "l"(a), "l"(b));
}
__device__ __forceinline__ unsigned long long pk2(float x, float y) {
    unsigned long long r;
    asm("mov.b64 %0, {%1, %2};" : "=l"(r) : "f"(x), "f"(y));
    return r;
}
__device__ __forceinline__ void upk2(float& x, float& y, unsigned long long v) {
    asm("mov.b64 {%0, %1}, %2;" : "=f"(x), "=f"(y) : "l"(v));
}
__device__ __forceinline__ void ldg2x64(unsigned long long& a, unsigned long long& b, const void* p) {
    asm("ld.global.v2.u64 {%0, %1}, [%2];" : "=l"(a), "=l"(b) : "l"(p));
}
__device__ __forceinline__ void stg2x64(void* p, unsigned long long a, unsigned long long b) {
    asm("st.global.v2.u64 [%0], {%1, %2};" :: "l"(p), "l"(a), "l"(b) : "memory");
}

// ------------------------ K_prep: pack weights, fold dst-half, zero accumulators ------------------------
__global__ void k_prep(const float* __restrict__ Wm0, const float* __restrict__ Wm1,
                       const float* __restrict__ Wm2,
                       const float* __restrict__ bm0, const float* __restrict__ bm1,
                       const float* __restrict__ bm2,
                       const float* __restrict__ ef0, const float* __restrict__ ef1,
                       const float* __restrict__ ef2,
                       const float* __restrict__ Wn0, const float* __restrict__ Wa0,
                       const float* __restrict__ Wn1, const float* __restrict__ Wa1,
                       const float* __restrict__ Wu, int N) {
    const float* Wm[3] = {Wm0, Wm1, Wm2};
    const float* bm[3] = {bm0, bm1, bm2};
    const float* ef[3] = {ef0, ef1, ef2};
    int tid = blockIdx.x * blockDim.x + threadIdx.x;
    int stride = blockDim.x * gridDim.x;

    // ---- zero accumulators ----
    {
        int accq = 3 * N * NSG;
        float4 z4 = make_float4(0.f, 0.f, 0.f, 0.f);
        for (int i = tid; i < accq; i += stride) g_acc4[i] = z4;
        for (int i = tid; i < 3 * N; i += stride) g_den[i] = 0.f;
    }

    // ---- W2: src halves + attention fold, [96 x 292] ----
    float* W2 = (float*)g_W2;
    for (int idx = tid; idx < H * PW2; idx += stride) {
        int k = idx / PW2, c = idx % PW2;
        float v;
        if (c < 288) {                     // src-half rows [0:96) of Wm_t
            int t = c / 96, j = c % 96;
            v = Wm[t][k * 96 + j];
        } else {                           // folded attention vectors Wn @ Wa-half
            int which = c - 288;           // 0:a_s0 1:a_d0 2:a_s1 3:a_d1
            const float* Wn = (which < 2) ? Wn0 : Wn1;
            const float* Wa = (which < 2) ? Wa0 : Wa1;
            int off = (which & 1) * 32;
            float s = 0.f;
            #pragma unroll
            for (int j = 0; j < 32; j++) s += Wn[k * 32 + j] * Wa[off + j];
            v = s;
        }
        W2[idx] = v;
    }
    // ---- c_t[j] = bm_t[j] + ef_t . Wm_t[192:208, j] ----
    for (int idx = tid; idx < 3 * H; idx += stride) {
        int t = idx / 96, j = idx % 96;
        float s = bm[t][j];
        #pragma unroll
        for (int i = 0; i < 16; i++) s += ef[t][i] * Wm[t][(192 + i) * 96 + j];
        g_C[idx] = s;
    }
    // ---- Wf[k][j]: k<96 -> Wu_h + sum_t Wdst_t@Wu_t ; k>=96 -> Wu row ----
    float* Wf = (float*)g_Wf;
    for (int idx = tid; idx < 384 * H; idx += stride) {
        int k = idx / 96, j = idx % 96;
        float v = Wu[k * 96 + j];
        if (k < 96) {
            #pragma unroll
            for (int t = 0; t < 3; t++) {
                const float* wm = Wm[t];
                float s = 0.f;
                #pragma unroll 8
                for (int i = 0; i < 96; i++)
                    s += wm[(96 + k) * 96 + i] * Wu[(96 + 96 * t + i) * 96 + j];
                v += s;
            }
        }
        Wf[k * 96 + j] = v;
    }
    // ---- Mneg[t][k][j] = -(Wdst_t @ Wu_t)[k][j]  (empty-node correction) ----
    float* Mn = (float*)g_Mneg;
    for (int idx = tid; idx < 3 * H * H; idx += stride) {
        int t = idx / (96 * 96), r = idx % (96 * 96);
        int k = r / 96, j = r % 96;
        const float* wm = Wm[t];
        float s = 0.f;
        #pragma unroll 8
        for (int i = 0; i < 96; i++)
            s += wm[(96 + k) * 96 + i] * Wu[(96 + 96 * t + i) * 96 + j];
        Mn[(t * 96 + k) * 96 + j] = -s;
    }
}

// ------------------------ K_node: packed GEMM [N x 96] @ [96 x 292], W prefetched ------------------------
static constexpr int TN = 64;              // node tile
__global__ void __launch_bounds__(256, 4) k_node(const float* __restrict__ h, int N) {
    __shared__ unsigned long long hs2[TN * H];   // 48KB
    int n0 = blockIdx.x * TN;
    int tid = threadIdx.x;

    for (int idx = tid; idx < TN * (H / 4); idx += 256) {   // 1536 float4
        int n = idx / (H / 4);
        int c4 = idx % (H / 4);
        float4 v = make_float4(0.f, 0.f, 0.f, 0.f);
        if (n0 + n < N) v = ((const float4*)h)[(size_t)(n0 + n) * (H / 4) + c4];
        int base = n * H + c4 * 4;
        hs2[base + 0] = pk2(v.x, v.x);
        hs2[base + 1] = pk2(v.y, v.y);
        hs2[base + 2] = pk2(v.z, v.z);
        hs2[base + 3] = pk2(v.w, v.w);
    }
    __syncthreads();

    for (int task = tid; task < NCG2 * (TN / 8); task += 256) {
        int cg = task % NCG2;              // adjacent threads -> adjacent cg (coalesced W)
        int nb = (task / NCG2) * 8;        // node sub-tile base
        const float4* Wp = g_W2 + cg;
        const unsigned long long* hp = &hs2[nb * H];

        unsigned long long a0[8], a1[8];
        #pragma unroll
        for (int i = 0; i < 8; i++) { a0[i] = 0ull; a1[i] = 0ull; }

        unsigned long long w0, w1;
        ldg2x64(w0, w1, Wp);               // k=0
        #pragma unroll 4
        for (int k = 0; k < H; k++) {
            unsigned long long nw0, nw1;
            ldg2x64(nw0, nw1, Wp + (size_t)(k + 1) * NCG2);   // prefetch (pad row at k=95)
            #pragma unroll
            for (int i = 0; i < 8; i++) {
                unsigned long long hh = hp[i * H + k];   // LDS.64 broadcast
                fma2(a0[i], hh, w0);
                fma2(a1[i], hh, w1);
            }
            w0 = nw0; w1 = nw1;
        }

        if (cg < 72) {
            int t = cg / NSG, off = cg % NSG;
            #pragma unroll
            for (int i = 0; i < 8; i++) {
                int n = n0 + nb + i;
                if (n < N)
                    stg2x64(&g_src4[((size_t)t * N + n) * NSG + off], a0[i], a1[i]);
            }
        } else {                            // cg==72: attention scalars (cols 288-291)
            #pragma unroll
            for (int i = 0; i < 8; i++) {
                int n = n0 + nb + i;
                if (n < N) stg2x64(&g_attn[n], a0[i], a1[i]);
            }
        }
    }
}

// ------------------------ K_scatter: 4 edges per warp, batched-MLP gather/red ------------------------
__global__ void __launch_bounds__(256) k_scatter(
        const int* __restrict__ src0, const int* __restrict__ dst0,
        const int* __restrict__ src1, const int* __restrict__ dst1,
        const int* __restrict__ src2, const int* __restrict__ dst2,
        int E, int N) {
    const unsigned FULL = 0xffffffffu;
    int gw   = (blockIdx.x * blockDim.x + threadIdx.x) >> 5;
    int lane = threadIdx.x & 31;
    int wpt  = (E + 3) >> 2;               // warps per edge type
    if (gw >= 3 * wpt) return;
    int t  = gw / wpt;
    int e0 = (gw - t * wpt) * 4;

    const int* sp = (t == 0) ? src0 : (t == 1) ? src1 : src2;
    const int* dp = (t == 0) ? dst0 : (t == 1) ? dst1 : dst2;
    const float4* sb = g_src4 + (size_t)t * N * NSG;   // 384B-aligned rows
    float4* ab = g_acc4 + (size_t)t * N * NSG;

    // lanes 0-3 load src[e0+lane], lanes 4-7 load dst[e0+lane-4]  (MLP=8)
    int idx = 0;
    if (lane < 8) {
        int e = e0 + (lane & 3);
        if (e < E) idx = (lane < 4) ? sp[e] : dp[e];
    }
    int dsh = __shfl_down_sync(FULL, idx, 4);   // lanes 0-3: their edge's dst

    // lanes 0-3: per-edge weight + den atomic
    float w = 1.f;
    if (lane < 4 && e0 + lane < E) {
        if (t < 2) {
            float4 as = g_attn[idx];
            float4 ad = g_attn[dsh];
            float x  = t ? (as.z + ad.w) : (as.x + ad.y);
            float sc = (x > 0.f) ? x : 0.01f * x;    // leaky_relu(0.01)
            w = __expf(sc);
        }
        atomicAdd(&g_den[t * N + dsh], w);
    }

    // batched gathers: 4 independent LDG.128 chains in flight
    float4 v[4];
    int    dj[4];
    float  wj[4];
    #pragma unroll
    for (int j = 0; j < 4; j++) {
        int s  = __shfl_sync(FULL, idx, j);
        dj[j]  = __shfl_sync(FULL, idx, 4 + j);
        wj[j]  = __shfl_sync(FULL, w, j);
        if (lane < 24 && e0 + j < E)
            v[j] = sb[(size_t)s * NSG + lane];
    }
    #pragma unroll
    for (int j = 0; j < 4; j++) {
        if (lane < 24 && e0 + j < E) {
            float4* a = &ab[(size_t)dj[j] * NSG + lane];
            float ww = wj[j];
            asm volatile("red.global.add.v4.f32 [%0], {%1,%2,%3,%4};"
                         :: "l"(a), "f"(v[j].x * ww), "f"(v[j].y * ww),
                            "f"(v[j].z * ww), "f"(v[j].w * ww)
                         : "memory");
        }
    }
}

// ------------------------ K_final v5: K-chunked, W-prefetched [N x 384] @ [384 x 96] ------------------------
// 48-node tile, 192 threads, 5 blocks/SM (30 warps). 4 K-chunks of 96; per chunk stage dup-packed
// (x,x) tile (36.8KB), inner loop: prefetched LDG.128(W) + 3 LDS.128(x) + 12 FFMA2 per k.
__global__ void __launch_bounds__(192, 5) k_final(const float* __restrict__ h,
                                                  const float* __restrict__ bu,
                                                  float* __restrict__ out, int N) {
    extern __shared__ unsigned long long dynsm[];
    unsigned long long* xs2 = dynsm;                    // [96][TF] dup pairs
    float* rden = (float*)(dynsm + 96 * TF);            // [TF][3]
    int n0 = blockIdx.x * TF;
    int tid = threadIdx.x;

    // stage reciprocals once per (node, type); 0 marks an empty mailbox. TF*3 = 144 < 192.
    if (tid < TF * 3) {
        int n = tid / 3, t = tid % 3;
        float den = (n0 + n < N) ? g_den[t * N + n0 + n] : 1.f;
        rden[n * 3 + t] = (den > 0.f) ? 1.0f / den : 0.f;
    }

    int cg = tid % 24;                     // output float4 group (coalesced W)
    int nb = (tid / 24) * 6;               // 6 nodes per thread

    float4 b = ((const float4*)bu)[cg];
    unsigned long long a0[6], a1[6];
    #pragma unroll
    for (int i = 0; i < 6; i++) { a0[i] = pk2(b.x, b.y); a1[i] = pk2(b.z, b.w); }

    for (int c = 0; c < 4; c++) {
        __syncthreads();                   // first iter: publishes rden; later: retire xs2 readers
        // stage chunk c: 48 nodes x 24 float4 cols
        for (int ep = tid; ep < TF * 24; ep += 192) {
            int n = ep / 24, j4 = ep % 24;
            int gn = n0 + n;
            float4 v = make_float4(0.f, 0.f, 0.f, 0.f);
            if (gn < N) {
                if (c == 0) {
                    v = ((const float4*)h)[(size_t)gn * 24 + j4];
                } else {
                    int t = c - 1;
                    float rd = rden[n * 3 + t];
                    if (rd > 0.f) {
                        float4 a = g_acc4[((size_t)t * N + gn) * NSG + j4];
                        float4 C = ((const float4*)g_C)[t * 24 + j4];
                        v.x = fmaf(a.x, rd, C.x); v.y = fmaf(a.y, rd, C.y);
                        v.z = fmaf(a.z, rd, C.z); v.w = fmaf(a.w, rd, C.w);
                    }
                }
            }
            int jb = j4 * 4;
            xs2[(jb + 0) * TF + n] = pk2(v.x, v.x);
            xs2[(jb + 1) * TF + n] = pk2(v.y, v.y);
            xs2[(jb + 2) * TF + n] = pk2(v.z, v.z);
            xs2[(jb + 3) * TF + n] = pk2(v.w, v.w);
        }
        __syncthreads();

        const float4* Wp = g_Wf + (size_t)c * 96 * 24 + cg;
        unsigned long long w0, w1;
        ldg2x64(w0, w1, Wp);               // k=0
        #pragma unroll 4
        for (int k = 0; k < 96; k++) {
            unsigned long long nw0, nw1;
            ldg2x64(nw0, nw1, Wp + (size_t)(k + 1) * 24);   // prefetch (pad row at chunk end)
            const ulonglong2* xk = (const ulonglong2*)&xs2[k * TF + nb];   // 16B-aligned (nb*8 % 16 == 0)
            ulonglong2 x01 = xk[0], x23 = xk[1], x45 = xk[2];
            fma2(a0[0], x01.x, w0); fma2(a1[0], x01.x, w1);
            fma2(a0[1], x01.y, w0); fma2(a1[1], x01.y, w1);
            fma2(a0[2], x23.x, w0); fma2(a1[2], x23.x, w1);
            fma2(a0[3], x23.y, w0); fma2(a1[3], x23.y, w1);
            fma2(a0[4], x45.x, w0); fma2(a1[4], x45.x, w1);
            fma2(a0[5], x45.y, w0); fma2(a1[5], x45.y, w1);
            w0 = nw0; w1 = nw1;
        }
    }

    // epilogue: rare empty-mailbox correction (x_h @ Mneg_t), relu, store
    #pragma unroll
    for (int i = 0; i < 6; i++) {
        int n = n0 + nb + i;
        if (n < N) {
            #pragma unroll
            for (int t = 0; t < 3; t++) {
                if (rden[(nb + i) * 3 + t] == 0.f) {
                    const float4* Mp = g_Mneg + (size_t)t * H * 24 + cg;
                    for (int k = 0; k < H; k++) {
                        unsigned long long m0, m1;
                        ldg2x64(m0, m1, Mp + (size_t)k * 24);
                        float hv = h[(size_t)n * 96 + k];
                        unsigned long long hh = pk2(hv, hv);
                        fma2(a0[i], hh, m0);
                        fma2(a1[i], hh, m1);
                    }
                }
            }
            float4 r;
            upk2(r.x, r.y, a0[i]);
            upk2(r.z, r.w, a1[i]);
            r.x = fmaxf(r.x, 0.f); r.y = fmaxf(r.y, 0.f);
            r.z = fmaxf(r.z, 0.f); r.w = fmaxf(r.w, 0.f);
            ((float4*)out)[(size_t)n * 24 + cg] = r;
        }
    }
}

// ------------------------ launch ------------------------
extern "C" void kernel_launch(void* const* d_in, const int* in_sizes, int n_in,
                              void* d_out, int out_size) {
    const float* h    = (const float*)d_in[0];
    const int*   src0 = (const int*)d_in[1];
    const int*   dst0 = (const int*)d_in[2];
    const int*   src1 = (const int*)d_in[3];
    const int*   dst1 = (const int*)d_in[4];
    const int*   src2 = (const int*)d_in[5];
    const int*   dst2 = (const int*)d_in[6];
    const float* Wm0  = (const float*)d_in[7];
    const float* bm0  = (const float*)d_in[8];
    const float* ef0  = (const float*)d_in[9];
    const float* Wm1  = (const float*)d_in[10];
    const float* bm1  = (const float*)d_in[11];
    const float* ef1  = (const float*)d_in[12];
    const float* Wm2  = (const float*)d_in[13];
    const float* bm2  = (const float*)d_in[14];
    const float* ef2  = (const float*)d_in[15];
    const float* Wn0  = (const float*)d_in[16];
    const float* Wa0  = (const float*)d_in[17];
    const float* Wn1  = (const float*)d_in[18];
    const float* Wa1  = (const float*)d_in[19];
    const float* Wu   = (const float*)d_in[20];
    const float* bu   = (const float*)d_in[21];

    int N = in_sizes[0] / H;
    int E = in_sizes[1];

    static bool attr_set = false;
    if (!attr_set) {
        cudaFuncSetAttribute(k_final, cudaFuncAttributeMaxDynamicSharedMemorySize, SMF);
        attr_set = true;
    }

    k_prep<<<256, 256>>>(Wm0, Wm1, Wm2, bm0, bm1, bm2, ef0, ef1, ef2,
                         Wn0, Wa0, Wn1, Wa1, Wu, N);
    k_node<<<(N + TN - 1) / TN, 256>>>(h, N);
    int wpt = (E + 3) / 4;
    long warps = 3L * wpt;
    k_scatter<<<(unsigned)((warps + 7) / 8), 256>>>(src0, dst0, src1, dst1, src2, dst2, E, N);
    k_final<<<(N + TF - 1) / TF, 192, SMF>>>(h, bu, (float*)d_out, N);
}